// round 15
// baseline (speedup 1.0000x reference)
#include <cuda_runtime.h>
#include <cstdint>

#define B_ 16
#define N_ 256
#define S_ 4096
#define C_ 512
#define H_ 8
#define HD 64
#define NCHUNK 8
#define SCHUNK (S_ / NCHUNK)   // 512

// Scratch (allocation-free: __device__ globals)
__device__ float g_kproj[(size_t)B_ * S_ * C_];              // 134 MB
__device__ float g_qproj[(size_t)B_ * N_ * C_];              // 8 MB
__device__ float g_opart[(size_t)B_ * H_ * NCHUNK * N_ * HD]; // 32 MB
__device__ float g_divpart[(size_t)B_ * H_ * NCHUNK * N_];

__device__ __forceinline__ uint32_t tf32u(float x) {
    uint32_t u;
    asm("cvt.rna.tf32.f32 %0, %1;" : "=r"(u) : "f"(x));
    return u;
}
__device__ __forceinline__ float tf32f(float x) {
    return __uint_as_float(tf32u(x));
}

__device__ __forceinline__ void mma_tf32(
    float& c0, float& c1, float& c2, float& c3,
    uint32_t a0, uint32_t a1, uint32_t a2, uint32_t a3,
    uint32_t b0, uint32_t b1)
{
    asm volatile(
        "mma.sync.aligned.m16n8k8.row.col.f32.tf32.tf32.f32 "
        "{%0,%1,%2,%3}, {%4,%5,%6,%7}, {%8,%9}, {%0,%1,%2,%3};"
        : "+f"(c0), "+f"(c1), "+f"(c2), "+f"(c3)
        : "r"(a0), "r"(a1), "r"(a2), "r"(a3), "r"(b0), "r"(b1));
}

__device__ __forceinline__ void cp_async16(uint32_t dst, const void* src) {
    asm volatile("cp.async.cg.shared.global [%0], [%1], 16;" :: "r"(dst), "l"(src));
}

// ---------------------------------------------------------------------------
// tf32 GEMM v4: A tiles pass through registers and land in smem in
// FRAGMENT-MAJOR layout [wm][ks][mf][lane^ks][4regs]; mainloop A-fragment =
// one LDS.128, zero CVT. W stays cp.async row-major. 2-stage, 2 CTAs/SM.
// C[M,512] = A[M,512] @ W[512,512]; block 128x128, 8 warps, K-tile 32.
// ---------------------------------------------------------------------------
#define WS_STRIDE 136
#define AFRAG_FLOATS 4096                 // one stage of fragment-major A
#define WBUF_FLOATS (32 * WS_STRIDE)      // 4352
#define GEMM_SMEM_BYTES ((2 * AFRAG_FLOATS + 2 * WBUF_FLOATS) * 4)  // 67584

__global__ __launch_bounds__(256, 2) void gemm_tf32_kernel(
    const float* __restrict__ A, const float* __restrict__ W,
    float* __restrict__ Cout)
{
    extern __shared__ float smbuf[];
    float* Afrag = smbuf;                         // [2][4096]
    float* Wbuf  = smbuf + 2 * AFRAG_FLOATS;      // [2][4352]
    uint32_t wsm;
    {
        uint64_t tmp = __cvta_generic_to_shared(Wbuf);
        wsm = (uint32_t)tmp;
    }

    const int tid  = threadIdx.x;
    const int warp = tid >> 5, lane = tid & 31;
    const int wm = warp >> 2, wn = warp & 3;
    const int group = lane >> 2, tid4 = lane & 3;
    const int m0 = blockIdx.x * 128, n0 = blockIdx.y * 128;

    // Per-thread A-load coords + fragment-store bases.
    // Thread i-th float4: row r, cols c0..c0+3 of the 128x32 K-tile.
    int rA[4];            // gmem row
    int cA[4];            // col offset within ktile (multiple of 4)
    int Cbase[4];         // float index within a stage (excl. t4 part)
    int sw[4];            // ks swizzle for this chunk
#pragma unroll
    for (int i = 0; i < 4; i++) {
        int f = tid + i * 256;
        int r = f >> 3, c0 = (f & 7) << 2;
        rA[i] = r; cA[i] = c0;
        int wms = r >> 6, mfs = (r >> 4) & 3, gs = r & 7, hs = (r >> 3) & 1;
        int kss = c0 >> 3, qs = (c0 >> 2) & 1;
        Cbase[i] = ((((wms * 4 + kss) * 4 + mfs) * 32) + gs * 4) * 4 + hs + 2 * qs;
        sw[i] = kss;      // ks < 4 here (ktile has 4 ks blocks)
    }
    int wr[4], wc4[4];
#pragma unroll
    for (int i = 0; i < 4; i++) {
        int f = tid + i * 256;
        wr[i] = f >> 5;  wc4[i] = (f & 31) << 2;
    }

    float acc[4][4][4];
#pragma unroll
    for (int mf = 0; mf < 4; mf++)
#pragma unroll
        for (int nf = 0; nf < 4; nf++)
#pragma unroll
            for (int r = 0; r < 4; r++) acc[mf][nf][r] = 0.f;

    float4 av[4];

#define LDG_A(kt)                                                              \
    do {                                                                       \
        _Pragma("unroll")                                                      \
        for (int i = 0; i < 4; i++)                                            \
            av[i] = *(const float4*)(A + (size_t)(m0 + rA[i]) * C_ +           \
                                     (kt) * 32 + cA[i]);                       \
    } while (0)

#define STS_A(s)                                                               \
    do {                                                                       \
        float* dst = Afrag + (s) * AFRAG_FLOATS;                               \
        _Pragma("unroll")                                                      \
        for (int i = 0; i < 4; i++) {                                          \
            dst[Cbase[i] + ((0 ^ sw[i]) << 2)] = tf32f(av[i].x);               \
            dst[Cbase[i] + ((1 ^ sw[i]) << 2)] = tf32f(av[i].y);               \
            dst[Cbase[i] + ((2 ^ sw[i]) << 2)] = tf32f(av[i].z);               \
            dst[Cbase[i] + ((3 ^ sw[i]) << 2)] = tf32f(av[i].w);               \
        }                                                                      \
    } while (0)

#define CP_W(kt, s)                                                            \
    do {                                                                       \
        uint32_t sb = wsm + (uint32_t)((s) * WBUF_FLOATS) * 4;                 \
        _Pragma("unroll")                                                      \
        for (int i = 0; i < 4; i++)                                            \
            cp_async16(sb + (uint32_t)(wr[i] * WS_STRIDE + wc4[i]) * 4,        \
                       W + (size_t)((kt) * 32 + wr[i]) * C_ + n0 + wc4[i]);    \
        asm volatile("cp.async.commit_group;");                                \
    } while (0)

    // Prologue: stage 0 fully staged, stage 1 in flight.
    LDG_A(0);
    CP_W(0, 0);
    STS_A(0);
    LDG_A(1);
    CP_W(1, 1);

    for (int kt = 0; kt < 16; kt++) {
        if (kt < 15) asm volatile("cp.async.wait_group 1;");
        else         asm volatile("cp.async.wait_group 0;");
        __syncthreads();   // stage (kt) A + W visible to all warps

        const float* Af = Afrag + (kt & 1) * AFRAG_FLOATS;
        const float* Ws = Wbuf + (kt & 1) * WBUF_FLOATS;

#pragma unroll
        for (int ks = 0; ks < 4; ks++) {
            const int kb = ks * 8;
            uint32_t a[4][4], b[4][2];
#pragma unroll
            for (int mf = 0; mf < 4; mf++) {
                float4 va = *(const float4*)&Af[((((wm * 4 + ks) * 4 + mf) * 32)
                                                 + (lane ^ ks)) * 4];
                a[mf][0] = __float_as_uint(va.x);
                a[mf][1] = __float_as_uint(va.y);
                a[mf][2] = __float_as_uint(va.z);
                a[mf][3] = __float_as_uint(va.w);
            }
#pragma unroll
            for (int nf = 0; nf < 4; nf++) {
                int c = wn * 32 + nf * 8 + group;
                b[nf][0] = tf32u(Ws[(kb + tid4) * WS_STRIDE + c]);
                b[nf][1] = tf32u(Ws[(kb + tid4 + 4) * WS_STRIDE + c]);
            }
#pragma unroll
            for (int mf = 0; mf < 4; mf++)
#pragma unroll
                for (int nf = 0; nf < 4; nf++)
                    mma_tf32(acc[mf][nf][0], acc[mf][nf][1],
                             acc[mf][nf][2], acc[mf][nf][3],
                             a[mf][0], a[mf][1], a[mf][2], a[mf][3],
                             b[nf][0], b[nf][1]);
        }
        __syncthreads();   // all warps done reading stage (kt) buffers

        if (kt + 1 < 16) STS_A((kt + 1) & 1);          // av holds kt+1
        if (kt + 2 < 16) {
            LDG_A(kt + 2);                              // safe: STS read av first
            CP_W(kt + 2, kt & 1);                       // buffer freed by sync
        }
    }

#pragma unroll
    for (int mf = 0; mf < 4; mf++) {
#pragma unroll
        for (int nf = 0; nf < 4; nf++) {
            int r = m0 + wm * 64 + mf * 16 + group;
            int c = n0 + wn * 32 + nf * 8 + 2 * tid4;
            *(float2*)(Cout + (size_t)r * C_ + c) =
                make_float2(acc[mf][nf][0], acc[mf][nf][1]);
            *(float2*)(Cout + (size_t)(r + 8) * C_ + c) =
                make_float2(acc[mf][nf][2], acc[mf][nf][3]);
        }
    }
}

// ---------------------------------------------------------------------------
// Attention (exact R5 body — unchanged).
// ---------------------------------------------------------------------------
#define ST 68
#define ATTN_SMEM_FLOATS (256 * ST + 64 * ST + 64 * ST + 256 + 64)
#define ATTN_SMEM_BYTES (ATTN_SMEM_FLOATS * 4)

__global__ __launch_bounds__(256) void attn_kernel(const float* __restrict__ keyv)
{
    extern __shared__ float sm[];
    float* sc     = sm;                 // [256][ST]
    float* Ks     = sm + 256 * ST;      // [64][ST]
    float* Vs     = Ks + 64 * ST;       // [64][ST]
    float* red    = Vs + 64 * ST;       // [4][64]
    float* colrcp = red + 256;          // [64]

    const int tid = threadIdx.x;
    const int warp = tid >> 5, lane = tid & 31;
    const int g = lane >> 2, t4 = lane & 3;
    const int chk = blockIdx.x, h = blockIdx.y, b = blockIdx.z;
    const int rb = warp * 32;
    const int col = tid & 63, part = tid >> 6;

    uint32_t qa[2][8][4];
    {
        const float* qp = g_qproj + (size_t)b * N_ * C_ + h * HD;
#pragma unroll
        for (int mf = 0; mf < 2; mf++) {
            int r0 = rb + mf * 16 + g;
#pragma unroll
            for (int kb = 0; kb < 8; kb++) {
                qa[mf][kb][0] = tf32u(qp[(size_t)r0 * C_ + kb * 8 + t4] * 0.125f);
                qa[mf][kb][1] = tf32u(qp[(size_t)(r0 + 8) * C_ + kb * 8 + t4] * 0.125f);
                qa[mf][kb][2] = tf32u(qp[(size_t)r0 * C_ + kb * 8 + t4 + 4] * 0.125f);
                qa[mf][kb][3] = tf32u(qp[(size_t)(r0 + 8) * C_ + kb * 8 + t4 + 4] * 0.125f);
            }
        }
    }

    float oa[2][8][4];
#pragma unroll
    for (int mf = 0; mf < 2; mf++)
#pragma unroll
        for (int nf = 0; nf < 8; nf++)
#pragma unroll
            for (int r = 0; r < 4; r++) oa[mf][nf][r] = 0.f;
    float dv[2][2] = {{0.f, 0.f}, {0.f, 0.f}};

    for (int tile = 0; tile < SCHUNK / 64; tile++) {
        const int s0 = chk * SCHUNK + tile * 64;
#pragma unroll
        for (int i = 0; i < 4; i++) {
            int f = tid + i * 256;
            int row = f >> 4, c4 = (f & 15) << 2;
            size_t gb = (size_t)(b * S_ + s0 + row) * C_ + h * HD + c4;
            *(float4*)&Ks[row * ST + c4] = *(const float4*)(g_kproj + gb);
            *(float4*)&Vs[row * ST + c4] = *(const float4*)(keyv + gb);
        }
        __syncthreads();

        float sacc[2][8][4];
#pragma unroll
        for (int mf = 0; mf < 2; mf++)
#pragma unroll
            for (int nf = 0; nf < 8; nf++)
#pragma unroll
                for (int r = 0; r < 4; r++) sacc[mf][nf][r] = 0.f;
#pragma unroll
        for (int kb = 0; kb < 8; kb++) {
            uint32_t bfr[8][2];
#pragma unroll
            for (int nf = 0; nf < 8; nf++) {
                bfr[nf][0] = tf32u(Ks[(nf * 8 + g) * ST + kb * 8 + t4]);
                bfr[nf][1] = tf32u(Ks[(nf * 8 + g) * ST + kb * 8 + t4 + 4]);
            }
#pragma unroll
            for (int mf = 0; mf < 2; mf++)
#pragma unroll
                for (int nf = 0; nf < 8; nf++)
                    mma_tf32(sacc[mf][nf][0], sacc[mf][nf][1],
                             sacc[mf][nf][2], sacc[mf][nf][3],
                             qa[mf][kb][0], qa[mf][kb][1], qa[mf][kb][2], qa[mf][kb][3],
                             bfr[nf][0], bfr[nf][1]);
        }
#pragma unroll
        for (int mf = 0; mf < 2; mf++)
#pragma unroll
            for (int nf = 0; nf < 8; nf++) {
                int r = rb + mf * 16 + g;
                int c = nf * 8 + 2 * t4;
                *(float2*)&sc[r * ST + c] = make_float2(sacc[mf][nf][0], sacc[mf][nf][1]);
                *(float2*)&sc[(r + 8) * ST + c] = make_float2(sacc[mf][nf][2], sacc[mf][nf][3]);
            }
        __syncthreads();

        float psum = 0.f;
#pragma unroll 4
        for (int r = 0; r < 64; r++) {
            int i = (part * 64 + r) * ST + col;
            float e = __expf(sc[i]);
            sc[i] = e;
            psum += e;
        }
        red[part * 64 + col] = psum;
        __syncthreads();
        if (part == 0)
            colrcp[col] = 1.0f / (red[col] + red[64 + col] + red[128 + col] + red[192 + col]);
        __syncthreads();

#pragma unroll
        for (int kb = 0; kb < 8; kb++) {
            float cr0 = colrcp[kb * 8 + t4], cr1 = colrcp[kb * 8 + t4 + 4];
            uint32_t afr[2][4];
#pragma unroll
            for (int mf = 0; mf < 2; mf++) {
                int r = rb + mf * 16 + g;
                float f0 = sc[r * ST + kb * 8 + t4] * cr0;
                float f1 = sc[(r + 8) * ST + kb * 8 + t4] * cr0;
                float f2 = sc[r * ST + kb * 8 + t4 + 4] * cr1;
                float f3 = sc[(r + 8) * ST + kb * 8 + t4 + 4] * cr1;
                dv[mf][0] += f0 + f2;
                dv[mf][1] += f1 + f3;
                afr[mf][0] = tf32u(f0); afr[mf][1] = tf32u(f1);
                afr[mf][2] = tf32u(f2); afr[mf][3] = tf32u(f3);
            }
            uint32_t bfr[8][2];
#pragma unroll
            for (int nf = 0; nf < 8; nf++) {
                bfr[nf][0] = tf32u(Vs[(kb * 8 + t4) * ST + nf * 8 + g]);
                bfr[nf][1] = tf32u(Vs[(kb * 8 + t4 + 4) * ST + nf * 8 + g]);
            }
#pragma unroll
            for (int mf = 0; mf < 2; mf++)
#pragma unroll
                for (int nf = 0; nf < 8; nf++)
                    mma_tf32(oa[mf][nf][0], oa[mf][nf][1],
                             oa[mf][nf][2], oa[mf][nf][3],
                             afr[mf][0], afr[mf][1], afr[mf][2], afr[mf][3],
                             bfr[nf][0], bfr[nf][1]);
        }
        __syncthreads();
    }

#pragma unroll
    for (int mf = 0; mf < 2; mf++)
#pragma unroll
        for (int hh = 0; hh < 2; hh++) {
            float v = dv[mf][hh];
            v += __shfl_xor_sync(0xFFFFFFFF, v, 1);
            v += __shfl_xor_sync(0xFFFFFFFF, v, 2);
            if (t4 == 0) {
                int row = rb + mf * 16 + hh * 8 + g;
                g_divpart[(size_t)((b * H_ + h) * NCHUNK + chk) * N_ + row] = v;
            }
        }

    const size_t pbase = (size_t)((b * H_ + h) * NCHUNK + chk) * N_;
#pragma unroll
    for (int mf = 0; mf < 2; mf++)
#pragma unroll
        for (int nf = 0; nf < 8; nf++) {
            int r = rb + mf * 16 + g;
            int c = nf * 8 + 2 * t4;
            *(float2*)(g_opart + (pbase + r) * HD + c) =
                make_float2(oa[mf][nf][0], oa[mf][nf][1]);
            *(float2*)(g_opart + (pbase + r + 8) * HD + c) =
                make_float2(oa[mf][nf][2], oa[mf][nf][3]);
        }
}

// ---------------------------------------------------------------------------
__global__ __launch_bounds__(256) void finalize_kernel(float* __restrict__ out)
{
    int idx = blockIdx.x * 256 + threadIdx.x;
    int c512 = idx & 511;
    int n = (idx >> 9) & 255;
    int b = idx >> 17;
    int h = c512 >> 6, c = c512 & 63;
    float acc = 0.f, dvs = 0.f;
#pragma unroll
    for (int chk = 0; chk < NCHUNK; chk++) {
        size_t pidx = (size_t)((b * H_ + h) * NCHUNK + chk) * N_ + n;
        acc += g_opart[pidx * HD + c];
        dvs += g_divpart[pidx];
    }
    float r = acc / fmaxf(dvs, 1.0f);
    out[idx] = r;
    out[idx + (size_t)B_ * N_ * C_] = r;
}

// ---------------------------------------------------------------------------
extern "C" void kernel_launch(void* const* d_in, const int* in_sizes, int n_in,
                              void* d_out, int out_size)
{
    const float* query = (const float*)d_in[0];
    const float* key   = (const float*)d_in[1];
    const float* Wq    = (const float*)d_in[2];
    const float* Wk    = (const float*)d_in[3];
    float* out = (float*)d_out;

    (void)in_sizes; (void)n_in; (void)out_size;

    cudaFuncSetAttribute(gemm_tf32_kernel,
                         cudaFuncAttributeMaxDynamicSharedMemorySize,
                         GEMM_SMEM_BYTES);
    cudaFuncSetAttribute(attn_kernel,
                         cudaFuncAttributeMaxDynamicSharedMemorySize,
                         ATTN_SMEM_BYTES);

    void* kp = nullptr; void* qp = nullptr;
    cudaGetSymbolAddress(&kp, g_kproj);
    cudaGetSymbolAddress(&qp, g_qproj);

    // Projections (tf32, fragment-major A staging, 2-stage, 2 CTAs/SM)
    gemm_tf32_kernel<<<dim3((B_ * S_) / 128, C_ / 128), 256, GEMM_SMEM_BYTES>>>(
        key, Wk, (float*)kp);
    gemm_tf32_kernel<<<dim3((B_ * N_) / 128, C_ / 128), 256, GEMM_SMEM_BYTES>>>(
        query, Wq, (float*)qp);

    // Attention (tensor-core, streaming over S chunks) — R5 body
    attn_kernel<<<dim3(NCHUNK, H_, B_), 256, ATTN_SMEM_BYTES>>>(key);

    // Reduce chunks + clamp-normalize + duplicate outputs
    finalize_kernel<<<(B_ * N_ * C_) / 256, 256>>>(out);
}